// round 1
// baseline (speedup 1.0000x reference)
#include <cuda_runtime.h>

#define NN 50000
#define EE 800000
#define LATD 64

// ---------------- scratch (static device memory; no allocations) ----------------
__device__ int   g_deg[NN];
__device__ int   g_rowptr[NN + 1];
__device__ int   g_cursor[NN];
__device__ int   g_col[EE];
__device__ float g_invdeg[NN];
__device__ float g_agg[NN * 128];
__device__ float g_h1m[NN * 128];
__device__ float g_h1v[NN * 128];
__device__ float g_h2m[NN * 128];
__device__ float g_h2v[NN * 128];

// ---------------- CSR build ----------------
__global__ void k_zero_deg() {
    int i = blockIdx.x * blockDim.x + threadIdx.x;
    if (i < NN) g_deg[i] = 0;
}

__global__ void k_count(const int* __restrict__ ei) {
    int e = blockIdx.x * blockDim.x + threadIdx.x;
    if (e < EE) atomicAdd(&g_deg[ei[EE + e]], 1);
}

// single-block exclusive scan over g_deg -> g_rowptr, also inv_deg and cursor copy
__global__ void k_scan() {
    __shared__ int s[1024];
    const int C = (NN + 1023) / 1024;  // 49
    int t = threadIdx.x;
    int base = t * C;
    int local = 0;
    for (int i = 0; i < C; i++) {
        int idx = base + i;
        if (idx < NN) local += g_deg[idx];
    }
    s[t] = local;
    __syncthreads();
    // Hillis-Steele inclusive scan
    for (int off = 1; off < 1024; off <<= 1) {
        int add = (t >= off) ? s[t - off] : 0;
        __syncthreads();
        s[t] += add;
        __syncthreads();
    }
    int prefix = (t > 0) ? s[t - 1] : 0;
    for (int i = 0; i < C; i++) {
        int idx = base + i;
        if (idx < NN) {
            int d = g_deg[idx];
            g_rowptr[idx] = prefix;
            g_cursor[idx] = prefix;
            g_invdeg[idx] = 1.0f / fmaxf((float)d, 1.0f);
            prefix += d;
        }
    }
    if (t == 1023) g_rowptr[NN] = prefix;  // == EE
}

__global__ void k_fill(const int* __restrict__ ei) {
    int e = blockIdx.x * blockDim.x + threadIdx.x;
    if (e < EE) {
        int d = ei[EE + e];
        int p = atomicAdd(&g_cursor[d], 1);
        g_col[p] = ei[e];
    }
}

// ---------------- SpMM (mean aggregation): one warp per node ----------------
template <int D>
__global__ void k_spmm(const float* __restrict__ h) {
    int w = (blockIdx.x * blockDim.x + threadIdx.x) >> 5;
    int lane = threadIdx.x & 31;
    if (w >= NN) return;
    int beg = g_rowptr[w], end = g_rowptr[w + 1];
    constexpr int V = D / 32;  // 2 or 4 floats/lane
    float acc[V];
#pragma unroll
    for (int i = 0; i < V; i++) acc[i] = 0.0f;
    for (int e = beg; e < end; e++) {
        const float* r = h + (size_t)g_col[e] * D + lane * V;
        if (V == 4) {
            float4 t = *(const float4*)r;
            acc[0] += t.x; acc[1] += t.y; acc[2] += t.z; acc[3] += t.w;
        } else {
            float2 t = *(const float2*)r;
            acc[0] += t.x; acc[1] += t.y;
        }
    }
    float sc = g_invdeg[w];
    float* o = g_agg + (size_t)w * D + lane * V;
#pragma unroll
    for (int i = 0; i < V; i++) o[i] = acc[i] * sc;
}

// ---------------- fused dual-GEMM (+bias, optional LN+ReLU) ----------------
// out[n, o] = sum_k agg[n,k]*Wl[o,k] + bl[o] + sum_k Ah[n,k]*Wr[o,k]
// if DOLN: out = relu((out - mean)*rstd*gamma + beta), LN over o.
template <int DIN, int DOUT, bool DOLN>
__global__ __launch_bounds__(256) void k_gemm(
    const float* __restrict__ Ah,
    const float* __restrict__ Wl, const float* __restrict__ bl,
    const float* __restrict__ Wr,
    const float* __restrict__ gam, const float* __restrict__ bet,
    float* __restrict__ out) {
    constexpr int TM = 8;
    constexpr int TN = DOUT / 16;

    __shared__ float As[128 * 17];
    __shared__ float Bs[16 * (DOUT + 1)];
    __shared__ float rsum[DOLN ? 128 * 16 : 1];
    __shared__ float rsq[DOLN ? 128 * 16 : 1];
    __shared__ float smean[DOLN ? 128 : 1];
    __shared__ float srstd[DOLN ? 128 : 1];

    int tid = threadIdx.x;
    int tx = tid & 15;
    int ty = tid >> 4;
    int m0 = blockIdx.x * 128;

    float c[TM][TN];
#pragma unroll
    for (int j = 0; j < TM; j++)
#pragma unroll
        for (int i = 0; i < TN; i++) c[j][i] = 0.0f;

#pragma unroll 1
    for (int phase = 0; phase < 2; phase++) {
        const float* A = phase ? Ah : g_agg;
        const float* W = phase ? Wr : Wl;
#pragma unroll 1
        for (int k0 = 0; k0 < DIN; k0 += 16) {
            __syncthreads();
#pragma unroll
            for (int l = tid; l < 128 * 16; l += 256) {
                int m = l >> 4, k = l & 15;
                int row = m0 + m;
                As[m * 17 + k] = (row < NN) ? A[(size_t)row * DIN + k0 + k] : 0.0f;
            }
#pragma unroll
            for (int l = tid; l < 16 * DOUT; l += 256) {
                int o = l >> 4, k = l & 15;
                Bs[k * (DOUT + 1) + o] = W[o * DIN + k0 + k];
            }
            __syncthreads();
#pragma unroll
            for (int k = 0; k < 16; k++) {
                float a[TM], b[TN];
#pragma unroll
                for (int j = 0; j < TM; j++) a[j] = As[(ty * TM + j) * 17 + k];
#pragma unroll
                for (int i = 0; i < TN; i++) b[i] = Bs[k * (DOUT + 1) + tx + 16 * i];
#pragma unroll
                for (int j = 0; j < TM; j++)
#pragma unroll
                    for (int i = 0; i < TN; i++) c[j][i] += a[j] * b[i];
            }
        }
    }

    // bias (must be added before LN stats)
#pragma unroll
    for (int i = 0; i < TN; i++) {
        float bv = bl[tx + 16 * i];
#pragma unroll
        for (int j = 0; j < TM; j++) c[j][i] += bv;
    }

    if (DOLN) {
        __syncthreads();
#pragma unroll
        for (int j = 0; j < TM; j++) {
            float s = 0.0f, q = 0.0f;
#pragma unroll
            for (int i = 0; i < TN; i++) { s += c[j][i]; q += c[j][i] * c[j][i]; }
            int row = ty * TM + j;
            rsum[row * 16 + tx] = s;
            rsq[row * 16 + tx] = q;
        }
        __syncthreads();
        if (tid < 128) {
            float s = 0.0f, q = 0.0f;
#pragma unroll
            for (int t = 0; t < 16; t++) { s += rsum[tid * 16 + t]; q += rsq[tid * 16 + t]; }
            float mean = s * (1.0f / DOUT);
            float var = q * (1.0f / DOUT) - mean * mean;
            smean[tid] = mean;
            srstd[tid] = rsqrtf(var + 1e-5f);
        }
        __syncthreads();
#pragma unroll
        for (int j = 0; j < TM; j++) {
            int row = ty * TM + j;
            int n = m0 + row;
            if (n < NN) {
                float mean = smean[row], rs = srstd[row];
#pragma unroll
                for (int i = 0; i < TN; i++) {
                    int o = tx + 16 * i;
                    float v = (c[j][i] - mean) * rs * gam[o] + bet[o];
                    out[(size_t)n * DOUT + o] = fmaxf(v, 0.0f);
                }
            }
        }
    } else {
#pragma unroll
        for (int j = 0; j < TM; j++) {
            int n = m0 + ty * TM + j;
            if (n < NN) {
#pragma unroll
                for (int i = 0; i < TN; i++) {
                    out[(size_t)n * DOUT + tx + 16 * i] = c[j][i];
                }
            }
        }
    }
}

// ---------------- launch ----------------
extern "C" void kernel_launch(void* const* d_in, const int* in_sizes, int n_in,
                              void* d_out, int out_size) {
    const float* x = (const float*)d_in[0];
    const int* ei = (const int*)d_in[1];
    const float* W[26];
    for (int i = 0; i < 26; i++) W[i] = (const float*)d_in[2 + i];
    // m tower: Wl0=0 bl0=1 Wr0=2 g0=3 b0=4 | Wl1=5 bl1=6 Wr1=7 g1=8 b1=9 | Wl2=10 bl2=11 Wr2=12
    // v tower: same + 13

    float *h1m, *h1v, *h2m, *h2v;
    cudaGetSymbolAddress((void**)&h1m, g_h1m);
    cudaGetSymbolAddress((void**)&h1v, g_h1v);
    cudaGetSymbolAddress((void**)&h2m, g_h2m);
    cudaGetSymbolAddress((void**)&h2v, g_h2v);

    float* out_mu = (float*)d_out;
    float* out_lv = out_mu + (size_t)NN * LATD;

    // CSR build
    k_zero_deg<<<(NN + 255) / 256, 256>>>();
    k_count<<<(EE + 255) / 256, 256>>>(ei);
    k_scan<<<1, 1024>>>();
    k_fill<<<(EE + 255) / 256, 256>>>(ei);

    const int WPB = 8;  // warps (nodes) per block
    const int SPMM_BLOCKS = (NN + WPB - 1) / WPB;
    const int GEMM_BLOCKS = (NN + 127) / 128;

    // layer 0 (agg of x shared between towers)
    k_spmm<64><<<SPMM_BLOCKS, 256>>>(x);
    k_gemm<64, 128, true><<<GEMM_BLOCKS, 256>>>(x, W[0], W[1], W[2], W[3], W[4], h1m);
    k_gemm<64, 128, true><<<GEMM_BLOCKS, 256>>>(x, W[13], W[14], W[15], W[16], W[17], h1v);

    // layer 1
    k_spmm<128><<<SPMM_BLOCKS, 256>>>(h1m);
    k_gemm<128, 128, true><<<GEMM_BLOCKS, 256>>>(h1m, W[5], W[6], W[7], W[8], W[9], h2m);
    k_spmm<128><<<SPMM_BLOCKS, 256>>>(h1v);
    k_gemm<128, 128, true><<<GEMM_BLOCKS, 256>>>(h1v, W[18], W[19], W[20], W[21], W[22], h2v);

    // layer 2 (no LN/ReLU)
    k_spmm<128><<<SPMM_BLOCKS, 256>>>(h2m);
    k_gemm<128, 64, false><<<GEMM_BLOCKS, 256>>>(h2m, W[10], W[11], W[12], nullptr, nullptr, out_mu);
    k_spmm<128><<<SPMM_BLOCKS, 256>>>(h2v);
    k_gemm<128, 64, false><<<GEMM_BLOCKS, 256>>>(h2v, W[23], W[24], W[25], nullptr, nullptr, out_lv);
}

// round 2
// speedup vs baseline: 1.7548x; 1.7548x over previous
#include <cuda_runtime.h>

#define NN 50000
#define EE 800000
#define LATD 64

// ---------------- scratch (static device memory; no allocations) ----------------
__device__ int   g_deg[NN];
__device__ int   g_rowptr[NN + 1];
__device__ int   g_cursor[NN];
__device__ int   g_col[EE];
__device__ float g_invdeg[NN];
__device__ float g_agg[NN * 128];
__device__ float g_h1m[NN * 128];
__device__ float g_h1v[NN * 128];
__device__ float g_h2m[NN * 128];
__device__ float g_h2v[NN * 128];

// ---------------- CSR build ----------------
__global__ void k_zero_deg() {
    int i = blockIdx.x * blockDim.x + threadIdx.x;
    if (i < NN) g_deg[i] = 0;
}

__global__ void k_count(const int* __restrict__ ei) {
    int e = blockIdx.x * blockDim.x + threadIdx.x;
    if (e < EE) atomicAdd(&g_deg[ei[EE + e]], 1);
}

__global__ void k_scan() {
    __shared__ int s[1024];
    const int C = (NN + 1023) / 1024;
    int t = threadIdx.x;
    int base = t * C;
    int local = 0;
    for (int i = 0; i < C; i++) {
        int idx = base + i;
        if (idx < NN) local += g_deg[idx];
    }
    s[t] = local;
    __syncthreads();
    for (int off = 1; off < 1024; off <<= 1) {
        int add = (t >= off) ? s[t - off] : 0;
        __syncthreads();
        s[t] += add;
        __syncthreads();
    }
    int prefix = (t > 0) ? s[t - 1] : 0;
    for (int i = 0; i < C; i++) {
        int idx = base + i;
        if (idx < NN) {
            int d = g_deg[idx];
            g_rowptr[idx] = prefix;
            g_cursor[idx] = prefix;
            g_invdeg[idx] = 1.0f / fmaxf((float)d, 1.0f);
            prefix += d;
        }
    }
    if (t == 1023) g_rowptr[NN] = prefix;
}

__global__ void k_fill(const int* __restrict__ ei) {
    int e = blockIdx.x * blockDim.x + threadIdx.x;
    if (e < EE) {
        int d = ei[EE + e];
        int p = atomicAdd(&g_cursor[d], 1);
        g_col[p] = ei[e];
    }
}

// ---------------- SpMM (mean aggregation): one warp per node ----------------
template <int D>
__global__ void k_spmm(const float* __restrict__ h) {
    int w = (blockIdx.x * blockDim.x + threadIdx.x) >> 5;
    int lane = threadIdx.x & 31;
    if (w >= NN) return;
    int beg = g_rowptr[w], end = g_rowptr[w + 1];
    constexpr int V = D / 32;
    float acc[V];
#pragma unroll
    for (int i = 0; i < V; i++) acc[i] = 0.0f;
    for (int e = beg; e < end; e++) {
        const float* r = h + (size_t)g_col[e] * D + lane * V;
        if (V == 4) {
            float4 t = *(const float4*)r;
            acc[0] += t.x; acc[1] += t.y; acc[2] += t.z; acc[3] += t.w;
        } else {
            float2 t = *(const float2*)r;
            acc[0] += t.x; acc[1] += t.y;
        }
    }
    float sc = g_invdeg[w];
    float* o = g_agg + (size_t)w * D + lane * V;
#pragma unroll
    for (int i = 0; i < V; i++) o[i] = acc[i] * sc;
}

// ---------------- tf32 tensor-core dual-GEMM (+bias, optional LN+ReLU) ----------------
__device__ __forceinline__ unsigned f2tf(float f) {
    unsigned u;
    asm("cvt.rna.tf32.f32 %0, %1;" : "=r"(u) : "f"(f));
    return u;
}

__device__ __forceinline__ void mma8(float* d, const unsigned* a, const unsigned* b) {
    asm volatile(
        "mma.sync.aligned.m16n8k8.row.col.f32.tf32.tf32.f32 "
        "{%0,%1,%2,%3}, {%4,%5,%6,%7}, {%8,%9}, {%0,%1,%2,%3};\n"
        : "+f"(d[0]), "+f"(d[1]), "+f"(d[2]), "+f"(d[3])
        : "r"(a[0]), "r"(a[1]), "r"(a[2]), "r"(a[3]), "r"(b[0]), "r"(b[1]));
}

// out[n,o] = sum_k agg[n,k]*Wl[o,k] + bl[o] + sum_k Ah[n,k]*Wr[o,k]; optional LN(gam,bet)+ReLU.
// Block tile: 128 x DOUT. 8 warps = 4(M) x 2(N). Warp tile: 32 x DOUT/2. K chunks of 32.
template <int DIN, int DOUT, bool DOLN>
__global__ __launch_bounds__(256) void k_gemm_tc(
    const float* __restrict__ Ah,
    const float* __restrict__ Wl, const float* __restrict__ bl,
    const float* __restrict__ Wr,
    const float* __restrict__ gam, const float* __restrict__ bet,
    float* __restrict__ out) {
    constexpr int NT = DOUT / 16;  // n-tiles (m16n8k8) per warp

    __shared__ unsigned As[128 * 36];
    __shared__ unsigned Bs[DOUT * 36];
    __shared__ float sS[DOLN ? 256 : 1];
    __shared__ float sQ[DOLN ? 256 : 1];
    __shared__ float sMean[DOLN ? 128 : 1];
    __shared__ float sRstd[DOLN ? 128 : 1];

    const int tid = threadIdx.x;
    const int lane = tid & 31;
    const int warp = tid >> 5;
    const int warpM = warp & 3;   // 0..3
    const int warpN = warp >> 2;  // 0..1
    const int g = lane >> 2;      // 0..7
    const int c = lane & 3;       // 0..3
    const int m0 = blockIdx.x * 128;

    float acc[2][NT][4];
#pragma unroll
    for (int mi = 0; mi < 2; mi++)
#pragma unroll
        for (int ni = 0; ni < NT; ni++)
#pragma unroll
            for (int r = 0; r < 4; r++) acc[mi][ni][r] = 0.0f;

#pragma unroll 1
    for (int phase = 0; phase < 2; phase++) {
        const float* A = phase ? Ah : g_agg;
        const float* W = phase ? Wr : Wl;
#pragma unroll 1
        for (int k0 = 0; k0 < DIN; k0 += 32) {
            __syncthreads();
            // A tile: 128 rows x 32 cols = 1024 float4 slots
#pragma unroll
            for (int i = 0; i < 4; i++) {
                int s = tid + i * 256;
                int m = s >> 3;
                int kq = (s & 7) * 4;
                int row = m0 + m;
                float4 v = make_float4(0.f, 0.f, 0.f, 0.f);
                if (row < NN) v = *(const float4*)(A + (size_t)row * DIN + k0 + kq);
                unsigned* p = &As[m * 36 + kq];
                p[0] = f2tf(v.x); p[1] = f2tf(v.y); p[2] = f2tf(v.z); p[3] = f2tf(v.w);
            }
            // B tile: DOUT rows x 32 cols
#pragma unroll
            for (int i = 0; i < DOUT * 8 / 256; i++) {
                int s = tid + i * 256;
                int n = s >> 3;
                int kq = (s & 7) * 4;
                float4 v = *(const float4*)(W + n * DIN + k0 + kq);
                unsigned* p = &Bs[n * 36 + kq];
                p[0] = f2tf(v.x); p[1] = f2tf(v.y); p[2] = f2tf(v.z); p[3] = f2tf(v.w);
            }
            __syncthreads();
#pragma unroll
            for (int ks = 0; ks < 4; ks++) {
                int kk = ks * 8;
                unsigned a[2][4];
#pragma unroll
                for (int mi = 0; mi < 2; mi++) {
                    int mb = warpM * 32 + mi * 16;
                    a[mi][0] = As[(mb + g) * 36 + kk + c];
                    a[mi][1] = As[(mb + g + 8) * 36 + kk + c];
                    a[mi][2] = As[(mb + g) * 36 + kk + c + 4];
                    a[mi][3] = As[(mb + g + 8) * 36 + kk + c + 4];
                }
                unsigned b[NT][2];
#pragma unroll
                for (int ni = 0; ni < NT; ni++) {
                    int nb = warpN * (DOUT / 2) + ni * 8;
                    b[ni][0] = Bs[(nb + g) * 36 + kk + c];
                    b[ni][1] = Bs[(nb + g) * 36 + kk + c + 4];
                }
#pragma unroll
                for (int mi = 0; mi < 2; mi++)
#pragma unroll
                    for (int ni = 0; ni < NT; ni++) mma8(acc[mi][ni], a[mi], b[ni]);
            }
        }
    }

    // bias (before LN stats)
#pragma unroll
    for (int ni = 0; ni < NT; ni++) {
        int col = warpN * (DOUT / 2) + ni * 8 + 2 * c;
        float b0 = bl[col], b1 = bl[col + 1];
#pragma unroll
        for (int mi = 0; mi < 2; mi++) {
            acc[mi][ni][0] += b0; acc[mi][ni][1] += b1;
            acc[mi][ni][2] += b0; acc[mi][ni][3] += b1;
        }
    }

    if (DOLN) {
#pragma unroll
        for (int mi = 0; mi < 2; mi++)
#pragma unroll
            for (int h = 0; h < 2; h++) {
                float s = 0.f, q = 0.f;
#pragma unroll
                for (int ni = 0; ni < NT; ni++) {
                    float v0 = acc[mi][ni][2 * h], v1 = acc[mi][ni][2 * h + 1];
                    s += v0 + v1;
                    q += v0 * v0 + v1 * v1;
                }
                s += __shfl_xor_sync(0xffffffffu, s, 1);
                s += __shfl_xor_sync(0xffffffffu, s, 2);
                q += __shfl_xor_sync(0xffffffffu, q, 1);
                q += __shfl_xor_sync(0xffffffffu, q, 2);
                if (c == 0) {
                    int row = warpM * 32 + mi * 16 + h * 8 + g;
                    sS[row * 2 + warpN] = s;
                    sQ[row * 2 + warpN] = q;
                }
            }
        __syncthreads();
        if (tid < 128) {
            float s = sS[tid * 2] + sS[tid * 2 + 1];
            float q = sQ[tid * 2] + sQ[tid * 2 + 1];
            float mean = s * (1.0f / DOUT);
            float var = q * (1.0f / DOUT) - mean * mean;
            sMean[tid] = mean;
            sRstd[tid] = rsqrtf(var + 1e-5f);
        }
        __syncthreads();
#pragma unroll
        for (int mi = 0; mi < 2; mi++)
#pragma unroll
            for (int h = 0; h < 2; h++) {
                int row = warpM * 32 + mi * 16 + h * 8 + g;
                int n = m0 + row;
                if (n < NN) {
                    float mean = sMean[row], rs = sRstd[row];
#pragma unroll
                    for (int ni = 0; ni < NT; ni++) {
                        int col = warpN * (DOUT / 2) + ni * 8 + 2 * c;
                        float v0 = (acc[mi][ni][2 * h] - mean) * rs * gam[col] + bet[col];
                        float v1 = (acc[mi][ni][2 * h + 1] - mean) * rs * gam[col + 1] + bet[col + 1];
                        float2 o;
                        o.x = fmaxf(v0, 0.0f);
                        o.y = fmaxf(v1, 0.0f);
                        *(float2*)(out + (size_t)n * DOUT + col) = o;
                    }
                }
            }
    } else {
#pragma unroll
        for (int mi = 0; mi < 2; mi++)
#pragma unroll
            for (int h = 0; h < 2; h++) {
                int row = warpM * 32 + mi * 16 + h * 8 + g;
                int n = m0 + row;
                if (n < NN) {
#pragma unroll
                    for (int ni = 0; ni < NT; ni++) {
                        int col = warpN * (DOUT / 2) + ni * 8 + 2 * c;
                        float2 o;
                        o.x = acc[mi][ni][2 * h];
                        o.y = acc[mi][ni][2 * h + 1];
                        *(float2*)(out + (size_t)n * DOUT + col) = o;
                    }
                }
            }
    }
}

// ---------------- launch ----------------
extern "C" void kernel_launch(void* const* d_in, const int* in_sizes, int n_in,
                              void* d_out, int out_size) {
    const float* x = (const float*)d_in[0];
    const int* ei = (const int*)d_in[1];
    const float* W[26];
    for (int i = 0; i < 26; i++) W[i] = (const float*)d_in[2 + i];

    float *h1m, *h1v, *h2m, *h2v;
    cudaGetSymbolAddress((void**)&h1m, g_h1m);
    cudaGetSymbolAddress((void**)&h1v, g_h1v);
    cudaGetSymbolAddress((void**)&h2m, g_h2m);
    cudaGetSymbolAddress((void**)&h2v, g_h2v);

    float* out_mu = (float*)d_out;
    float* out_lv = out_mu + (size_t)NN * LATD;

    // CSR build
    k_zero_deg<<<(NN + 255) / 256, 256>>>();
    k_count<<<(EE + 255) / 256, 256>>>(ei);
    k_scan<<<1, 1024>>>();
    k_fill<<<(EE + 255) / 256, 256>>>(ei);

    const int WPB = 8;
    const int SPMM_BLOCKS = (NN + WPB - 1) / WPB;
    const int GEMM_BLOCKS = (NN + 127) / 128;

    // layer 0 (agg of x shared between towers)
    k_spmm<64><<<SPMM_BLOCKS, 256>>>(x);
    k_gemm_tc<64, 128, true><<<GEMM_BLOCKS, 256>>>(x, W[0], W[1], W[2], W[3], W[4], h1m);
    k_gemm_tc<64, 128, true><<<GEMM_BLOCKS, 256>>>(x, W[13], W[14], W[15], W[16], W[17], h1v);

    // layer 1
    k_spmm<128><<<SPMM_BLOCKS, 256>>>(h1m);
    k_gemm_tc<128, 128, true><<<GEMM_BLOCKS, 256>>>(h1m, W[5], W[6], W[7], W[8], W[9], h2m);
    k_spmm<128><<<SPMM_BLOCKS, 256>>>(h1v);
    k_gemm_tc<128, 128, true><<<GEMM_BLOCKS, 256>>>(h1v, W[18], W[19], W[20], W[21], W[22], h2v);

    // layer 2 (no LN/ReLU)
    k_spmm<128><<<SPMM_BLOCKS, 256>>>(h2m);
    k_gemm_tc<128, 64, false><<<GEMM_BLOCKS, 256>>>(h2m, W[10], W[11], W[12], nullptr, nullptr, out_mu);
    k_spmm<128><<<SPMM_BLOCKS, 256>>>(h2v);
    k_gemm_tc<128, 64, false><<<GEMM_BLOCKS, 256>>>(h2v, W[23], W[24], W[25], nullptr, nullptr, out_lv);
}

// round 4
// speedup vs baseline: 2.5962x; 1.4795x over previous
#include <cuda_runtime.h>

#define NN 50000
#define EE 800000
#define LATD 64

// ---------------- scratch (static device memory; no allocations) ----------------
__device__ int   g_deg[NN];
__device__ int   g_rowptr[NN + 1];
__device__ int   g_cursor[NN];
__device__ int   g_col[EE];
__device__ float g_invdeg[NN];
__device__ float g_agg[NN * 128];   // layer0 agg (64-wide), layer1 agg m, layer2 PR m
__device__ float g_aggv[NN * 128];  // layer1 agg v, layer2 PR v
__device__ float g_h1m[NN * 128];
__device__ float g_h1v[NN * 128];
__device__ float g_h2m[NN * 128];
__device__ float g_h2v[NN * 128];

// ---------------- CSR build ----------------
__global__ void k_count(const int* __restrict__ ei) {
    int t = blockIdx.x * blockDim.x + threadIdx.x;
    int e = t * 4;
    if (e < EE) {
        int4 d = *(const int4*)(ei + EE + e);
        atomicAdd(&g_deg[d.x], 1);
        atomicAdd(&g_deg[d.y], 1);
        atomicAdd(&g_deg[d.z], 1);
        atomicAdd(&g_deg[d.w], 1);
    }
}

// coalesced warp-based scan: 32 warps, each owns a contiguous 1568-node segment
__global__ void k_scan() {
    __shared__ int wtot[32], wpre[32];
    const int SEG = 1568;  // 32*1568 = 50176 >= NN
    int tid = threadIdx.x, lane = tid & 31, w = tid >> 5;
    int base = w * SEG;
    int s = 0;
#pragma unroll
    for (int j = 0; j < SEG / 32; j++) {
        int idx = base + j * 32 + lane;
        if (idx < NN) s += g_deg[idx];
    }
#pragma unroll
    for (int o = 16; o; o >>= 1) s += __shfl_xor_sync(0xffffffffu, s, o);
    if (lane == 0) wtot[w] = s;
    __syncthreads();
    if (w == 0) {
        int v = wtot[lane];
        int inc = v;
#pragma unroll
        for (int o = 1; o < 32; o <<= 1) {
            int t = __shfl_up_sync(0xffffffffu, inc, o);
            if (lane >= o) inc += t;
        }
        wpre[lane] = inc - v;
    }
    __syncthreads();
    int run = wpre[w];
#pragma unroll 1
    for (int j = 0; j < SEG / 32; j++) {
        int idx = base + j * 32 + lane;
        int d = (idx < NN) ? g_deg[idx] : 0;
        int inc = d;
#pragma unroll
        for (int o = 1; o < 32; o <<= 1) {
            int t = __shfl_up_sync(0xffffffffu, inc, o);
            if (lane >= o) inc += t;
        }
        if (idx < NN) {
            int off = run + inc - d;
            g_rowptr[idx] = off;
            g_cursor[idx] = off;
            g_invdeg[idx] = 1.0f / fmaxf((float)d, 1.0f);
        }
        run += __shfl_sync(0xffffffffu, inc, 31);
    }
    if (tid == 0) g_rowptr[NN] = EE;
}

__global__ void k_fill(const int* __restrict__ ei) {
    int t = blockIdx.x * blockDim.x + threadIdx.x;
    int e = t * 4;
    if (e < EE) {
        int4 ss = *(const int4*)(ei + e);
        int4 dd = *(const int4*)(ei + EE + e);
        int p;
        p = atomicAdd(&g_cursor[dd.x], 1); g_col[p] = ss.x;
        p = atomicAdd(&g_cursor[dd.y], 1); g_col[p] = ss.y;
        p = atomicAdd(&g_cursor[dd.z], 1); g_col[p] = ss.z;
        p = atomicAdd(&g_cursor[dd.w], 1); g_col[p] = ss.w;
    }
}

// ---------------- SpMM kernels (warp per node) ----------------
// layer 0: agg of x (D=64) -> g_agg
__global__ void k_spmm0(const float* __restrict__ x) {
    int w = (blockIdx.x * blockDim.x + threadIdx.x) >> 5;
    int lane = threadIdx.x & 31;
    if (w >= NN) return;
    int beg = g_rowptr[w], end = g_rowptr[w + 1];
    float a0 = 0.f, a1 = 0.f;
    int e = beg;
    for (; e + 4 <= end; e += 4) {
        int c0 = g_col[e], c1 = g_col[e + 1], c2 = g_col[e + 2], c3 = g_col[e + 3];
        float2 t0 = *(const float2*)(x + (size_t)c0 * 64 + lane * 2);
        float2 t1 = *(const float2*)(x + (size_t)c1 * 64 + lane * 2);
        float2 t2 = *(const float2*)(x + (size_t)c2 * 64 + lane * 2);
        float2 t3 = *(const float2*)(x + (size_t)c3 * 64 + lane * 2);
        a0 += t0.x + t1.x + t2.x + t3.x;
        a1 += t0.y + t1.y + t2.y + t3.y;
    }
    for (; e < end; e++) {
        float2 t = *(const float2*)(x + (size_t)g_col[e] * 64 + lane * 2);
        a0 += t.x; a1 += t.y;
    }
    float sc = g_invdeg[w];
    float2 o; o.x = a0 * sc; o.y = a1 * sc;
    *(float2*)(g_agg + (size_t)w * 64 + lane * 2) = o;
}

// layer 1: dual-tower agg of h1m/h1v (D=128) -> g_agg / g_aggv
__global__ void k_spmm1d(const float* __restrict__ hm, const float* __restrict__ hv) {
    int w = (blockIdx.x * blockDim.x + threadIdx.x) >> 5;
    int lane = threadIdx.x & 31;
    if (w >= NN) return;
    int beg = g_rowptr[w], end = g_rowptr[w + 1];
    float m0 = 0.f, m1 = 0.f, m2 = 0.f, m3 = 0.f;
    float v0 = 0.f, v1 = 0.f, v2 = 0.f, v3 = 0.f;
    int e = beg;
    for (; e + 2 <= end; e += 2) {
        int c0 = g_col[e], c1 = g_col[e + 1];
        float4 tm0 = *(const float4*)(hm + (size_t)c0 * 128 + lane * 4);
        float4 tv0 = *(const float4*)(hv + (size_t)c0 * 128 + lane * 4);
        float4 tm1 = *(const float4*)(hm + (size_t)c1 * 128 + lane * 4);
        float4 tv1 = *(const float4*)(hv + (size_t)c1 * 128 + lane * 4);
        m0 += tm0.x + tm1.x; m1 += tm0.y + tm1.y; m2 += tm0.z + tm1.z; m3 += tm0.w + tm1.w;
        v0 += tv0.x + tv1.x; v1 += tv0.y + tv1.y; v2 += tv0.z + tv1.z; v3 += tv0.w + tv1.w;
    }
    for (; e < end; e++) {
        int c0 = g_col[e];
        float4 tm = *(const float4*)(hm + (size_t)c0 * 128 + lane * 4);
        float4 tv = *(const float4*)(hv + (size_t)c0 * 128 + lane * 4);
        m0 += tm.x; m1 += tm.y; m2 += tm.z; m3 += tm.w;
        v0 += tv.x; v1 += tv.y; v2 += tv.z; v3 += tv.w;
    }
    float sc = g_invdeg[w];
    float4 om; om.x = m0 * sc; om.y = m1 * sc; om.z = m2 * sc; om.w = m3 * sc;
    float4 ov; ov.x = v0 * sc; ov.y = v1 * sc; ov.z = v2 * sc; ov.w = v3 * sc;
    *(float4*)(g_agg + (size_t)w * 128 + lane * 4) = om;
    *(float4*)(g_aggv + (size_t)w * 128 + lane * 4) = ov;
}

// layer 2: out = S*P + R, where PR rows = [P(64) | R(64)]; dual tower, writes d_out
__global__ void k_spmm2d(const float* __restrict__ PRm, const float* __restrict__ PRv,
                         float* __restrict__ outm, float* __restrict__ outv) {
    int w = (blockIdx.x * blockDim.x + threadIdx.x) >> 5;
    int lane = threadIdx.x & 31;
    if (w >= NN) return;
    int beg = g_rowptr[w], end = g_rowptr[w + 1];
    float m0 = 0.f, m1 = 0.f, v0 = 0.f, v1 = 0.f;
    int e = beg;
    for (; e + 2 <= end; e += 2) {
        int c0 = g_col[e], c1 = g_col[e + 1];
        float2 tm0 = *(const float2*)(PRm + (size_t)c0 * 128 + lane * 2);
        float2 tv0 = *(const float2*)(PRv + (size_t)c0 * 128 + lane * 2);
        float2 tm1 = *(const float2*)(PRm + (size_t)c1 * 128 + lane * 2);
        float2 tv1 = *(const float2*)(PRv + (size_t)c1 * 128 + lane * 2);
        m0 += tm0.x + tm1.x; m1 += tm0.y + tm1.y;
        v0 += tv0.x + tv1.x; v1 += tv0.y + tv1.y;
    }
    for (; e < end; e++) {
        int c0 = g_col[e];
        float2 tm = *(const float2*)(PRm + (size_t)c0 * 128 + lane * 2);
        float2 tv = *(const float2*)(PRv + (size_t)c0 * 128 + lane * 2);
        m0 += tm.x; m1 += tm.y; v0 += tv.x; v1 += tv.y;
    }
    float sc = g_invdeg[w];
    float2 rm = *(const float2*)(PRm + (size_t)w * 128 + 64 + lane * 2);
    float2 rv = *(const float2*)(PRv + (size_t)w * 128 + 64 + lane * 2);
    float2 om; om.x = m0 * sc + rm.x; om.y = m1 * sc + rm.y;
    float2 ov; ov.x = v0 * sc + rv.x; ov.y = v1 * sc + rv.y;
    *(float2*)(outm + (size_t)w * 64 + lane * 2) = om;
    *(float2*)(outv + (size_t)w * 64 + lane * 2) = ov;
}

// ---------------- tf32 tensor-core GEMM ----------------
__device__ __forceinline__ unsigned f2tf(float f) {
    unsigned u;
    asm("cvt.rna.tf32.f32 %0, %1;" : "=r"(u) : "f"(f));
    return u;
}

__device__ __forceinline__ void mma8(float* d, const unsigned* a, const unsigned* b) {
    asm volatile(
        "mma.sync.aligned.m16n8k8.row.col.f32.tf32.tf32.f32 "
        "{%0,%1,%2,%3}, {%4,%5,%6,%7}, {%8,%9}, {%0,%1,%2,%3};\n"
        : "+f"(d[0]), "+f"(d[1]), "+f"(d[2]), "+f"(d[3])
        : "r"(a[0]), "r"(a[1]), "r"(a[2]), "r"(a[3]), "r"(b[0]), "r"(b[1]));
}

struct GArgs {
    const float *A0, *A1, *Wa, *Wb, *bias, *gam, *bet;
    float* out;
};

// MODE 0 (LN): out = LNReLU(A0@Wa^T + bias + A1@Wb^T), DOUT=128
// MODE 1 (PR): out[:,0:64] = A0@Wa^T ; out[:,64:128] = A0@Wb^T + bias
// Block tile 128 x 128, 8 warps = 4(M) x 2(N), warp tile 32x64, K chunks of 64.
template <int DIN, int MODE>
__global__ __launch_bounds__(256) void k_gemm_tc(GArgs am, GArgs av) {
    const GArgs A = blockIdx.y ? av : am;
    constexpr int DOUT = 128;
    constexpr int NT = DOUT / 16;  // 8

    extern __shared__ unsigned sh[];
    unsigned* As = sh;               // 128*68
    unsigned* Bs = sh + 128 * 68;    // 128*68
    __shared__ float sS[MODE == 0 ? 256 : 1];
    __shared__ float sQ[MODE == 0 ? 256 : 1];
    __shared__ float sMean[MODE == 0 ? 128 : 1];
    __shared__ float sRstd[MODE == 0 ? 128 : 1];

    const int tid = threadIdx.x;
    const int lane = tid & 31;
    const int warp = tid >> 5;
    const int warpM = warp & 3;
    const int warpN = warp >> 2;
    const int g = lane >> 2;
    const int c = lane & 3;
    const int m0 = blockIdx.x * 128;

    float acc[2][NT][4];
#pragma unroll
    for (int mi = 0; mi < 2; mi++)
#pragma unroll
        for (int ni = 0; ni < NT; ni++)
#pragma unroll
            for (int r = 0; r < 4; r++) acc[mi][ni][r] = 0.0f;

    constexpr int NPH = (MODE == 0) ? 2 : 1;
#pragma unroll 1
    for (int phase = 0; phase < NPH; phase++) {
        const float* Ap = (MODE == 0 && phase) ? A.A1 : A.A0;
#pragma unroll 1
        for (int k0 = 0; k0 < DIN; k0 += 64) {
            __syncthreads();
            // A tile: 128 rows x 64 cols (float4 quads)
#pragma unroll
            for (int i = 0; i < 8; i++) {
                int s = tid + i * 256;
                int m = s >> 4;
                int kq = (s & 15) * 4;
                int row = m0 + m;
                float4 v = make_float4(0.f, 0.f, 0.f, 0.f);
                if (row < NN) v = *(const float4*)(Ap + (size_t)row * DIN + k0 + kq);
                uint4 u;
                u.x = f2tf(v.x); u.y = f2tf(v.y); u.z = f2tf(v.z); u.w = f2tf(v.w);
                *(uint4*)&As[m * 68 + kq] = u;
            }
            // B tile: 128 rows x 64 cols
#pragma unroll
            for (int i = 0; i < 8; i++) {
                int s = tid + i * 256;
                int n = s >> 4;
                int kq = (s & 15) * 4;
                const float* Wrow;
                if (MODE == 1)
                    Wrow = (n < 64) ? (A.Wa + n * DIN) : (A.Wb + (n - 64) * DIN);
                else
                    Wrow = (phase ? A.Wb : A.Wa) + n * DIN;
                float4 v = *(const float4*)(Wrow + k0 + kq);
                uint4 u;
                u.x = f2tf(v.x); u.y = f2tf(v.y); u.z = f2tf(v.z); u.w = f2tf(v.w);
                *(uint4*)&Bs[n * 68 + kq] = u;
            }
            __syncthreads();
#pragma unroll
            for (int ks = 0; ks < 8; ks++) {
                int kk = ks * 8;
                unsigned a[2][4];
#pragma unroll
                for (int mi = 0; mi < 2; mi++) {
                    int mb = warpM * 32 + mi * 16;
                    a[mi][0] = As[(mb + g) * 68 + kk + c];
                    a[mi][1] = As[(mb + g + 8) * 68 + kk + c];
                    a[mi][2] = As[(mb + g) * 68 + kk + c + 4];
                    a[mi][3] = As[(mb + g + 8) * 68 + kk + c + 4];
                }
                unsigned b[NT][2];
#pragma unroll
                for (int ni = 0; ni < NT; ni++) {
                    int nb = warpN * 64 + ni * 8;
                    b[ni][0] = Bs[(nb + g) * 68 + kk + c];
                    b[ni][1] = Bs[(nb + g) * 68 + kk + c + 4];
                }
#pragma unroll
                for (int mi = 0; mi < 2; mi++)
#pragma unroll
                    for (int ni = 0; ni < NT; ni++) mma8(acc[mi][ni], a[mi], b[ni]);
            }
        }
    }

    // bias
    if (MODE == 0) {
#pragma unroll
        for (int ni = 0; ni < NT; ni++) {
            int col = warpN * 64 + ni * 8 + 2 * c;
            float b0 = A.bias[col], b1 = A.bias[col + 1];
#pragma unroll
            for (int mi = 0; mi < 2; mi++) {
                acc[mi][ni][0] += b0; acc[mi][ni][1] += b1;
                acc[mi][ni][2] += b0; acc[mi][ni][3] += b1;
            }
        }
    } else if (warpN == 1) {  // bias only on R half (cols 64..127)
#pragma unroll
        for (int ni = 0; ni < NT; ni++) {
            int cl = ni * 8 + 2 * c;
            float b0 = A.bias[cl], b1 = A.bias[cl + 1];
#pragma unroll
            for (int mi = 0; mi < 2; mi++) {
                acc[mi][ni][0] += b0; acc[mi][ni][1] += b1;
                acc[mi][ni][2] += b0; acc[mi][ni][3] += b1;
            }
        }
    }

    if (MODE == 0) {
#pragma unroll
        for (int mi = 0; mi < 2; mi++)
#pragma unroll
            for (int h = 0; h < 2; h++) {
                float s = 0.f, q = 0.f;
#pragma unroll
                for (int ni = 0; ni < NT; ni++) {
                    float u0 = acc[mi][ni][2 * h], u1 = acc[mi][ni][2 * h + 1];
                    s += u0 + u1;
                    q += u0 * u0 + u1 * u1;
                }
                s += __shfl_xor_sync(0xffffffffu, s, 1);
                s += __shfl_xor_sync(0xffffffffu, s, 2);
                q += __shfl_xor_sync(0xffffffffu, q, 1);
                q += __shfl_xor_sync(0xffffffffu, q, 2);
                if (c == 0) {
                    int row = warpM * 32 + mi * 16 + h * 8 + g;
                    sS[row * 2 + warpN] = s;
                    sQ[row * 2 + warpN] = q;
                }
            }
        __syncthreads();
        if (tid < 128) {
            float s = sS[tid * 2] + sS[tid * 2 + 1];
            float q = sQ[tid * 2] + sQ[tid * 2 + 1];
            float mean = s * (1.0f / 128);
            float var = q * (1.0f / 128) - mean * mean;
            sMean[tid] = mean;
            sRstd[tid] = rsqrtf(var + 1e-5f);
        }
        __syncthreads();
#pragma unroll
        for (int mi = 0; mi < 2; mi++)
#pragma unroll
            for (int h = 0; h < 2; h++) {
                int row = warpM * 32 + mi * 16 + h * 8 + g;
                int n = m0 + row;
                if (n < NN) {
                    float mean = sMean[row], rs = sRstd[row];
#pragma unroll
                    for (int ni = 0; ni < NT; ni++) {
                        int col = warpN * 64 + ni * 8 + 2 * c;
                        float u0 = (acc[mi][ni][2 * h] - mean) * rs * A.gam[col] + A.bet[col];
                        float u1 = (acc[mi][ni][2 * h + 1] - mean) * rs * A.gam[col + 1] + A.bet[col + 1];
                        float2 o;
                        o.x = fmaxf(u0, 0.0f);
                        o.y = fmaxf(u1, 0.0f);
                        *(float2*)(A.out + (size_t)n * 128 + col) = o;
                    }
                }
            }
    } else {
#pragma unroll
        for (int mi = 0; mi < 2; mi++)
#pragma unroll
            for (int h = 0; h < 2; h++) {
                int row = warpM * 32 + mi * 16 + h * 8 + g;
                int n = m0 + row;
                if (n < NN) {
#pragma unroll
                    for (int ni = 0; ni < NT; ni++) {
                        int col = warpN * 64 + ni * 8 + 2 * c;
                        float2 o;
                        o.x = acc[mi][ni][2 * h];
                        o.y = acc[mi][ni][2 * h + 1];
                        *(float2*)(A.out + (size_t)n * 128 + col) = o;
                    }
                }
            }
    }
}

// ---------------- launch ----------------
extern "C" void kernel_launch(void* const* d_in, const int* in_sizes, int n_in,
                              void* d_out, int out_size) {
    const float* x = (const float*)d_in[0];
    const int* ei = (const int*)d_in[1];
    const float* W[26];
    for (int i = 0; i < 26; i++) W[i] = (const float*)d_in[2 + i];
    // m: Wl0=0 bl0=1 Wr0=2 g0=3 b0=4 | Wl1=5 bl1=6 Wr1=7 g1=8 b1=9 | Wl2=10 bl2=11 Wr2=12; v=+13

    float *agg, *aggv, *h1m, *h1v, *h2m, *h2v;
    int* degp;
    cudaGetSymbolAddress((void**)&agg, g_agg);
    cudaGetSymbolAddress((void**)&aggv, g_aggv);
    cudaGetSymbolAddress((void**)&h1m, g_h1m);
    cudaGetSymbolAddress((void**)&h1v, g_h1v);
    cudaGetSymbolAddress((void**)&h2m, g_h2m);
    cudaGetSymbolAddress((void**)&h2v, g_h2v);
    cudaGetSymbolAddress((void**)&degp, g_deg);

    float* out_mu = (float*)d_out;
    float* out_lv = out_mu + (size_t)NN * LATD;

    const int SMEM = 2 * 128 * 68 * 4;  // 69632
    cudaFuncSetAttribute(k_gemm_tc<64, 0>, cudaFuncAttributeMaxDynamicSharedMemorySize, SMEM);
    cudaFuncSetAttribute(k_gemm_tc<128, 0>, cudaFuncAttributeMaxDynamicSharedMemorySize, SMEM);
    cudaFuncSetAttribute(k_gemm_tc<128, 1>, cudaFuncAttributeMaxDynamicSharedMemorySize, SMEM);

    // CSR build
    cudaMemsetAsync(degp, 0, NN * sizeof(int));
    k_count<<<(EE / 4 + 255) / 256, 256>>>(ei);
    k_scan<<<1, 1024>>>();
    k_fill<<<(EE / 4 + 255) / 256, 256>>>(ei);

    const int SPMM_BLOCKS = (NN + 7) / 8;  // 8 warps/block
    dim3 gg((NN + 127) / 128, 2);

    // layer 0
    k_spmm0<<<SPMM_BLOCKS, 256>>>(x);
    {
        GArgs am = {agg, x, W[0], W[2], W[1], W[3], W[4], h1m};
        GArgs av = {agg, x, W[13], W[15], W[14], W[16], W[17], h1v};
        k_gemm_tc<64, 0><<<gg, 256, SMEM>>>(am, av);
    }
    // layer 1
    k_spmm1d<<<SPMM_BLOCKS, 256>>>(h1m, h1v);
    {
        GArgs am = {agg, h1m, W[5], W[7], W[6], W[8], W[9], h2m};
        GArgs av = {aggv, h1v, W[18], W[20], W[19], W[21], W[22], h2v};
        k_gemm_tc<128, 0><<<gg, 256, SMEM>>>(am, av);
    }
    // layer 2: PR = [h2@Wl^T | h2@Wr^T + bl], then out = S*P + R
    {
        GArgs am = {h2m, nullptr, W[10], W[12], W[11], nullptr, nullptr, agg};
        GArgs av = {h2v, nullptr, W[23], W[25], W[24], nullptr, nullptr, aggv};
        k_gemm_tc<128, 1><<<gg, 256, SMEM>>>(am, av);
    }
    k_spmm2d<<<SPMM_BLOCKS, 256>>>(agg, aggv, out_mu, out_lv);
}